// round 1
// baseline (speedup 1.0000x reference)
#include <cuda_runtime.h>
#include <cstdint>

#define C1 64
#define C2 128
#define C3 256
#define DD 128
#define TM 128

// ---------------- static device scratch (no allocs allowed) ----------------
__device__ float g_y2[(size_t)131072 * DD];       // level-2 merged features
__device__ int   g_perm1[420000 + 4096];
__device__ int   g_perm2[131072 + 4096];
__device__ float g_B3[8 * 384 * DD];              // [k][384][128] = [W3@T3k ; W2]
__device__ float g_B2[8 * 192 * DD];              // [k][192][128] = [T2k ; W1]
__device__ int   g_cnt1[8], g_cnt2[8];
__device__ int   g_st1[9], g_st2[9];
__device__ int   g_cur1[8], g_cur2[8];

// ---------------- helpers ----------------
__device__ __forceinline__ float tfr(float x) {
    uint32_t u;
    asm("cvt.rna.tf32.f32 %0, %1;" : "=r"(u) : "f"(x));
    return __uint_as_float(u);
}

__device__ __forceinline__ void mma_tf32(float* c, const uint32_t* a, const uint32_t* b) {
    asm volatile(
        "mma.sync.aligned.m16n8k8.row.col.f32.tf32.tf32.f32 "
        "{%0,%1,%2,%3}, {%4,%5,%6,%7}, {%8,%9}, {%0,%1,%2,%3};\n"
        : "+f"(c[0]), "+f"(c[1]), "+f"(c[2]), "+f"(c[3])
        : "r"(a[0]), "r"(a[1]), "r"(a[2]), "r"(a[3]), "r"(b[0]), "r"(b[1]));
}

// ---------------- small kernels ----------------
__global__ void k_init(int* perm1, int n1p, int* perm2, int n2p, int* cnt1, int* cnt2) {
    int i = blockIdx.x * blockDim.x + threadIdx.x;
    int stride = gridDim.x * blockDim.x;
    for (int j = i; j < n1p; j += stride) perm1[j] = -1;
    for (int j = i; j < n2p; j += stride) perm2[j] = -1;
    if (i < 8) { cnt1[i] = 0; cnt2[i] = 0; }
}

__global__ void k_hist(const int* __restrict__ off, int n, int* cnt) {
    __shared__ int s[8];
    if (threadIdx.x < 8) s[threadIdx.x] = 0;
    __syncthreads();
    for (int i = blockIdx.x * blockDim.x + threadIdx.x; i < n; i += gridDim.x * blockDim.x)
        atomicAdd(&s[off[i]], 1);
    __syncthreads();
    if (threadIdx.x < 8) atomicAdd(&cnt[threadIdx.x], s[threadIdx.x]);
}

__global__ void k_scan(const int* cnt, int* starts, int* cur) {
    if (threadIdx.x == 0) {
        int run = 0;
        for (int k = 0; k < 8; k++) {
            starts[k] = run;
            cur[k] = run;
            run += ((cnt[k] + TM - 1) / TM) * TM;
        }
        starts[8] = run;
    }
}

__global__ void k_scatter(const int* __restrict__ off, int n, int* cur, int* perm) {
    for (int i = blockIdx.x * blockDim.x + threadIdx.x; i < n; i += gridDim.x * blockDim.x) {
        int p = atomicAdd(&cur[off[i]], 1);
        perm[p] = i;
    }
}

// B2[k] = [ T2[k] (128x128) ; W1 (64x128) ]  (tf32-rounded)
__global__ void k_build_b2(const float* __restrict__ T2, const float* __restrict__ W1, float* B) {
    int idx = blockIdx.x * blockDim.x + threadIdx.x;
    if (idx >= 8 * 192 * DD) return;
    int k = idx / (192 * DD);
    int r = (idx >> 7) % 192;
    int d = idx & 127;
    float v = (r < 128) ? T2[((size_t)k * 128 + r) * DD + d] : W1[(r - 128) * DD + d];
    B[idx] = tfr(v);
}

// B3[k] = [ W3@T3[k] (256x128) ; W2 (128x128) ]  (tf32-rounded)
__global__ void k_build_b3(const float* __restrict__ W3, const float* __restrict__ T3,
                           const float* __restrict__ W2, float* B) {
    int idx = blockIdx.x * blockDim.x + threadIdx.x;
    if (idx >= 8 * 384 * DD) return;
    int k = idx / (384 * DD);
    int r = (idx >> 7) % 384;
    int d = idx & 127;
    float v;
    if (r < 256) {
        float acc = 0.f;
        const float* w = W3 + (size_t)r * 128;
        const float* t = T3 + (size_t)k * 128 * DD + d;
#pragma unroll 8
        for (int e = 0; e < 128; e++) acc += w[e] * t[e * DD];
        v = acc;
    } else {
        v = W2[(size_t)(r - 256) * DD + d];
    }
    B[idx] = tfr(v);
}

// ---------------- main gather-GEMM ----------------
// out[gid] = concat(coarse[parent[gid]], fine[gid]) @ Bcat[bin]
template <int KTOT, int CSRC, int CFINE>
__global__ __launch_bounds__(256) void k_gemm(
    const float* __restrict__ coarse, const float* __restrict__ fine,
    const float* __restrict__ Bcat, const int* __restrict__ perm,
    const int* __restrict__ parent, const int* __restrict__ starts,
    float* __restrict__ out)
{
    __shared__ float As[128 * 36];   // 128 rows x 32 k, stride 36
    __shared__ float Bs[32 * 132];   // 32 k x 128 n, stride 132
    __shared__ int   s_gid[128];
    __shared__ int   s_starts[9];

    const int base = blockIdx.x * TM;
    if (threadIdx.x < 9) s_starts[threadIdx.x] = starts[threadIdx.x];
    if (threadIdx.x < 128) s_gid[threadIdx.x] = perm[base + threadIdx.x];
    __syncthreads();
    if (base >= s_starts[8]) return;

    int kb = 0;
    while (kb < 7 && base >= s_starts[kb + 1]) kb++;
    const float* Bk = Bcat + (size_t)kb * KTOT * DD;

    const int tid = threadIdx.x;
    const int r = tid >> 1, half = tid & 1;
    const int gid = s_gid[r];
    const float* pc = (gid >= 0) ? coarse + (size_t)parent[gid] * CSRC : nullptr;
    const float* pf = (gid >= 0) ? fine + (size_t)gid * CFINE : nullptr;

    const int warp = tid >> 5, lane = tid & 31, g = lane >> 2, tg = lane & 3;
    const int wm = warp & 1, wn = warp >> 1;

    float acc[4][4][4] = {};

    for (int kk = 0; kk < KTOT; kk += 32) {
        // ---- stage A (gathered, tf32-rounded) ----
        float* dA = As + r * 36 + half * 16;
        const float* src = nullptr;
        if (gid >= 0) src = (kk < CSRC) ? (pc + kk) : (pf + (kk - CSRC));
#pragma unroll
        for (int v = 0; v < 4; v++) {
            float4 x = src ? *(const float4*)(src + half * 16 + v * 4)
                           : make_float4(0.f, 0.f, 0.f, 0.f);
            x.x = tfr(x.x); x.y = tfr(x.y); x.z = tfr(x.z); x.w = tfr(x.w);
            *(float4*)(dA + v * 4) = x;
        }
        // ---- stage B (already tf32-rounded at build) ----
#pragma unroll
        for (int j = 0; j < 4; j++) {
            int fi = tid + j * 256;
            int kr = fi >> 5, c4 = fi & 31;
            *(float4*)(Bs + kr * 132 + c4 * 4) =
                *(const float4*)(Bk + (size_t)(kk + kr) * DD + c4 * 4);
        }
        __syncthreads();

        // ---- compute 4 k8-steps ----
#pragma unroll
        for (int ks = 0; ks < 4; ks++) {
            const int k8 = ks * 8;
            uint32_t af[4][4], bf[4][2];
#pragma unroll
            for (int mt = 0; mt < 4; mt++) {
                const float* ap = As + (wm * 64 + mt * 16 + g) * 36 + k8 + tg;
                af[mt][0] = __float_as_uint(ap[0]);
                af[mt][1] = __float_as_uint(ap[8 * 36]);
                af[mt][2] = __float_as_uint(ap[4]);
                af[mt][3] = __float_as_uint(ap[8 * 36 + 4]);
            }
#pragma unroll
            for (int nt = 0; nt < 4; nt++) {
                const float* bp = Bs + (k8 + tg) * 132 + wn * 32 + nt * 8 + g;
                bf[nt][0] = __float_as_uint(bp[0]);
                bf[nt][1] = __float_as_uint(bp[4 * 132]);
            }
#pragma unroll
            for (int mt = 0; mt < 4; mt++)
#pragma unroll
                for (int nt = 0; nt < 4; nt++)
                    mma_tf32(acc[mt][nt], af[mt], bf[nt]);
        }
        __syncthreads();
    }

    // ---- scatter store ----
#pragma unroll
    for (int mt = 0; mt < 4; mt++) {
        int row = wm * 64 + mt * 16 + g;
        int g0 = s_gid[row], g1 = s_gid[row + 8];
#pragma unroll
        for (int nt = 0; nt < 4; nt++) {
            int col = wn * 32 + nt * 8 + tg * 2;
            if (g0 >= 0)
                *(float2*)(out + (size_t)g0 * DD + col) =
                    make_float2(acc[mt][nt][0], acc[mt][nt][1]);
            if (g1 >= 0)
                *(float2*)(out + (size_t)g1 * DD + col) =
                    make_float2(acc[mt][nt][2], acc[mt][nt][3]);
        }
    }
}

// ---------------- launch ----------------
extern "C" void kernel_launch(void* const* d_in, const int* in_sizes, int n_in,
                              void* d_out, int out_size)
{
    const float* feats1  = (const float*)d_in[0];
    const float* feats2  = (const float*)d_in[1];
    const float* feats3  = (const float*)d_in[2];
    const int*   parent1 = (const int*)d_in[3];
    const int*   offset1 = (const int*)d_in[4];
    const int*   parent2 = (const int*)d_in[5];
    const int*   offset2 = (const int*)d_in[6];
    const float* W1 = (const float*)d_in[7];
    const float* W2 = (const float*)d_in[8];
    const float* W3 = (const float*)d_in[9];
    const float* T2 = (const float*)d_in[10];
    const float* T3 = (const float*)d_in[11];

    const int N1 = in_sizes[3];
    const int N2 = in_sizes[5];

    float *y2, *B2, *B3;
    int *perm1, *perm2, *cnt1, *cnt2, *st1, *st2, *cu1, *cu2;
    cudaGetSymbolAddress((void**)&y2, g_y2);
    cudaGetSymbolAddress((void**)&B2, g_B2);
    cudaGetSymbolAddress((void**)&B3, g_B3);
    cudaGetSymbolAddress((void**)&perm1, g_perm1);
    cudaGetSymbolAddress((void**)&perm2, g_perm2);
    cudaGetSymbolAddress((void**)&cnt1, g_cnt1);
    cudaGetSymbolAddress((void**)&cnt2, g_cnt2);
    cudaGetSymbolAddress((void**)&st1, g_st1);
    cudaGetSymbolAddress((void**)&st2, g_st2);
    cudaGetSymbolAddress((void**)&cu1, g_cur1);
    cudaGetSymbolAddress((void**)&cu2, g_cur2);

    const int tiles1 = (N1 + TM - 1) / TM + 8;
    const int tiles2 = (N2 + TM - 1) / TM + 8;
    const int n1p = tiles1 * TM;
    const int n2p = tiles2 * TM;

    k_init<<<512, 256>>>(perm1, n1p, perm2, n2p, cnt1, cnt2);
    k_hist<<<256, 256>>>(offset2, N2, cnt2);
    k_hist<<<512, 256>>>(offset1, N1, cnt1);
    k_scan<<<1, 32>>>(cnt2, st2, cu2);
    k_scan<<<1, 32>>>(cnt1, st1, cu1);
    k_scatter<<<256, 256>>>(offset2, N2, cu2, perm2);
    k_scatter<<<512, 256>>>(offset1, N1, cu1, perm1);
    k_build_b2<<<(8 * 192 * DD + 255) / 256, 256>>>(T2, W1, B2);
    k_build_b3<<<(8 * 384 * DD + 255) / 256, 256>>>(W3, T3, W2, B3);

    // level 3 -> 2 : y2 = gather_tconv(feats3@W3, T3) + feats2@W2
    k_gemm<384, C3, C2><<<tiles2, 256>>>(feats3, feats2, B3, perm2, parent2, st2, y2);
    // level 2 -> 1 : out = gather_tconv(y2, T2) + feats1@W1
    k_gemm<192, C2, C1><<<tiles1, 256>>>(y2, feats1, B2, perm1, parent1, st1, (float*)d_out);
}